// round 1
// baseline (speedup 1.0000x reference)
#include <cuda_runtime.h>

#define VOCAB 21128
#define EMB   768
#define HID   256
#define NTAGS 8
#define BATCH 64
#define SEQ   512
#define NTOK  (BATCH * SEQ)

#define TM 64     // tokens per block tile
#define KT 16     // K tile

// scratch (allocation-free rule: device globals)
__device__ float g_logits[NTOK * NTAGS];   // 1 MB: log_softmax outputs
__device__ float g_dctr[BATCH * HID];      // per-batch domain contribution incl. fc1_b

// ---------------------------------------------------------------------------
// Kernel 1: dctr[b][n] = fc1_b[n] + dom_w[corpus[b]] . fc1_w[n][768:1024]
// ---------------------------------------------------------------------------
__global__ void dom_kernel(const int* __restrict__ corpus,
                           const float* __restrict__ dom_w,
                           const float* __restrict__ fc1_w,
                           const float* __restrict__ fc1_b) {
    int b = blockIdx.x;
    int n = threadIdx.x;
    int c = corpus[b];
    const float* dw = dom_w + c * HID;
    const float* wr = fc1_w + n * (HID + EMB) + EMB;
    float acc = fc1_b[n];
#pragma unroll 8
    for (int k = 0; k < HID; k++) acc += dw[k] * wr[k];
    g_dctr[b * HID + n] = acc;
}

// ---------------------------------------------------------------------------
// Kernel 2: fused embed-gather + FC1(emb part) + dctr + relu + FC2 + log_softmax
// Block: 256 threads, TM=64 tokens x N=256 outputs. 8 warps: warp w owns token
// rows w*8..w*8+7 (A smem reads broadcast), lane owns cols lane+32*j
// (conflict-free B smem reads). acc[8][8] register tile per thread.
// ---------------------------------------------------------------------------
__global__ __launch_bounds__(256) void mlp_kernel(
    const int* __restrict__ words,
    const float* __restrict__ embed_w,
    const float* __restrict__ fc1_w,
    const float* __restrict__ fc2_w,
    const float* __restrict__ fc2_b) {

    __shared__ float As[TM][KT];          // 4 KB  (token rows x K-slice)
    __shared__ float Bs[KT][HID];         // 16 KB (K-slice x out cols)
    __shared__ float sD[HID];             // 1 KB  dctr for this batch elem
    __shared__ float sF2[NTAGS * HID];    // 8 KB  fc2_w
    __shared__ int   sWord[TM];

    const int tid  = threadIdx.x;
    const int tile = blockIdx.x;          // 0..511
    const int tok0 = tile * TM;           // tile never crosses batch boundary (512 % 64 == 0)
    const int b    = tok0 / SEQ;

    if (tid < TM) sWord[tid] = words[tok0 + tid];
    sD[tid] = g_dctr[b * HID + tid];
    for (int i = tid; i < NTAGS * HID; i += 256) sF2[i] = fc2_w[i];
    __syncthreads();

    const int w    = tid >> 5;            // warp id 0..7
    const int lane = tid & 31;

    // loader mapping: each thread loads 4 floats of one token row per K-tile
    const int lr = tid >> 2;              // 0..63
    const int lc = (tid & 3) * 4;         // 0,4,8,12
    const float* arow = embed_w + (long)sWord[lr] * EMB;
    const float* brow = fc1_w + tid * (HID + EMB);   // row tid, embedding cols

    float acc[8][8];
#pragma unroll
    for (int i = 0; i < 8; i++)
#pragma unroll
        for (int j = 0; j < 8; j++) acc[i][j] = 0.f;

    for (int k0 = 0; k0 < EMB; k0 += KT) {
        __syncthreads();
        // A tile: gathered embedding rows
        *(float4*)&As[lr][lc] = *(const float4*)(arow + k0 + lc);
        // B tile: fc1_w transposed slice, Bs[k][n]
        float4 b0 = *(const float4*)(brow + k0 + 0);
        float4 b1 = *(const float4*)(brow + k0 + 4);
        float4 b2 = *(const float4*)(brow + k0 + 8);
        float4 b3 = *(const float4*)(brow + k0 + 12);
        Bs[0][tid]  = b0.x; Bs[1][tid]  = b0.y; Bs[2][tid]  = b0.z; Bs[3][tid]  = b0.w;
        Bs[4][tid]  = b1.x; Bs[5][tid]  = b1.y; Bs[6][tid]  = b1.z; Bs[7][tid]  = b1.w;
        Bs[8][tid]  = b2.x; Bs[9][tid]  = b2.y; Bs[10][tid] = b2.z; Bs[11][tid] = b2.w;
        Bs[12][tid] = b3.x; Bs[13][tid] = b3.y; Bs[14][tid] = b3.z; Bs[15][tid] = b3.w;
        __syncthreads();

#pragma unroll
        for (int kk = 0; kk < KT; kk++) {
            float a[8], bb[8];
#pragma unroll
            for (int i = 0; i < 8; i++) a[i] = As[w * 8 + i][kk];   // broadcast
#pragma unroll
            for (int j = 0; j < 8; j++) bb[j] = Bs[kk][lane + 32 * j];
#pragma unroll
            for (int i = 0; i < 8; i++)
#pragma unroll
                for (int j = 0; j < 8; j++) acc[i][j] = fmaf(a[i], bb[j], acc[i][j]);
        }
    }

    // epilogue: + dctr (includes fc1_b), relu
    float d[8];
#pragma unroll
    for (int j = 0; j < 8; j++) d[j] = sD[lane + 32 * j];
#pragma unroll
    for (int i = 0; i < 8; i++)
#pragma unroll
        for (int j = 0; j < 8; j++) acc[i][j] = fmaxf(acc[i][j] + d[j], 0.f);

    // FC2 (8x256) + log_softmax, per token row owned by this warp
#pragma unroll
    for (int i = 0; i < 8; i++) {
        float pred[NTAGS];
#pragma unroll
        for (int t = 0; t < NTAGS; t++) {
            float p = 0.f;
#pragma unroll
            for (int j = 0; j < 8; j++)
                p = fmaf(acc[i][j], sF2[t * HID + lane + 32 * j], p);
#pragma unroll
            for (int off = 16; off > 0; off >>= 1)
                p += __shfl_down_sync(0xffffffffu, p, off);
            pred[t] = p;
        }
        if (lane == 0) {
            float mx = -1e30f;
#pragma unroll
            for (int t = 0; t < NTAGS; t++) {
                pred[t] += fc2_b[t];
                mx = fmaxf(mx, pred[t]);
            }
            float sm = 0.f;
#pragma unroll
            for (int t = 0; t < NTAGS; t++) sm += __expf(pred[t] - mx);
            float lse = mx + __logf(sm);
            int token = tok0 + w * 8 + i;
            float* o = g_logits + token * NTAGS;
#pragma unroll
            for (int t = 0; t < NTAGS; t++) o[t] = pred[t] - lse;
        }
    }
}

// ---------------------------------------------------------------------------
// Kernel 3: CRF forward (logsumexp scan) + gold path score + loss.
// 32 threads/block = 4 batch elems x 8 tag-lanes. 16 blocks.
// ---------------------------------------------------------------------------
__global__ void crf_kernel(const int* __restrict__ words,
                           const int* __restrict__ target,
                           const float* __restrict__ trans,
                           const float* __restrict__ start_s,
                           const float* __restrict__ end_s,
                           float* __restrict__ out) {
    const int lane = threadIdx.x;
    const int g    = lane >> 3;
    const int j    = lane & 7;
    const int b    = blockIdx.x * 4 + g;
    const int base = lane & ~7;

    const float* L  = g_logits + b * SEQ * NTAGS;
    const int* wds  = words  + b * SEQ;
    const int* tg   = target + b * SEQ;

    float tc[8];
#pragma unroll
    for (int i = 0; i < 8; i++) tc[i] = trans[i * NTAGS + j];

    float alpha = L[j] + start_s[j];

    for (int s = 1; s < SEQ; s++) {
        float emit = L[s * NTAGS + j];
        int m = (wds[s] != 0);
        float v[8];
        float mx = -1e30f;
#pragma unroll
        for (int i = 0; i < 8; i++) {
            float a = __shfl_sync(0xffffffffu, alpha, base + i);
            v[i] = a + tc[i];
            mx = fmaxf(mx, v[i]);
        }
        float sm = 0.f;
#pragma unroll
        for (int i = 0; i < 8; i++) sm += __expf(v[i] - mx);
        float nw = mx + __logf(sm) + emit;
        alpha = m ? nw : alpha;
    }

    // norm = logsumexp_j(alpha + end_s)
    float v = alpha + end_s[j];
    float mx = v;
#pragma unroll
    for (int d = 1; d < 8; d <<= 1) mx = fmaxf(mx, __shfl_xor_sync(0xffffffffu, mx, d));
    float sm = __expf(v - mx);
#pragma unroll
    for (int d = 1; d < 8; d <<= 1) sm += __shfl_xor_sync(0xffffffffu, sm, d);
    float norm = mx + __logf(sm);

    // gold path score: lanes stride over sequence positions
    float esum = 0.f, tsum = 0.f;
    int cnt = 0;
    for (int s = j; s < SEQ; s += 8) {
        int t = tg[s];
        int m = (wds[s] != 0);
        if (m) {
            esum += L[s * NTAGS + t];
            cnt++;
            if (s > 0) tsum += trans[tg[s - 1] * NTAGS + t];
        }
    }
#pragma unroll
    for (int d = 1; d < 8; d <<= 1) {
        esum += __shfl_xor_sync(0xffffffffu, esum, d);
        tsum += __shfl_xor_sync(0xffffffffu, tsum, d);
        cnt  += __shfl_xor_sync(0xffffffffu, cnt, d);
    }

    if (j == 0) {
        int last = cnt - 1;
        float score = esum + tsum + start_s[tg[0]] + end_s[tg[last]];
        out[b] = norm - score;
    }
}

// ---------------------------------------------------------------------------
extern "C" void kernel_launch(void* const* d_in, const int* in_sizes, int n_in,
                              void* d_out, int out_size) {
    const int*   words   = (const int*)  d_in[0];
    const int*   target  = (const int*)  d_in[1];
    const int*   corpus  = (const int*)  d_in[2];
    const float* embed_w = (const float*)d_in[3];
    const float* dom_w   = (const float*)d_in[4];
    const float* fc1_w   = (const float*)d_in[5];
    const float* fc1_b   = (const float*)d_in[6];
    const float* fc2_w   = (const float*)d_in[7];
    const float* fc2_b   = (const float*)d_in[8];
    const float* trans   = (const float*)d_in[9];
    const float* start_s = (const float*)d_in[10];
    const float* end_s   = (const float*)d_in[11];
    float* out = (float*)d_out;

    dom_kernel<<<BATCH, HID>>>(corpus, dom_w, fc1_w, fc1_b);
    mlp_kernel<<<NTOK / TM, 256>>>(words, embed_w, fc1_w, fc2_w, fc2_b);
    crf_kernel<<<BATCH / 4, 32>>>(words, target, trans, start_s, end_s, out);
}